// round 12
// baseline (speedup 1.0000x reference)
#include <cuda_runtime.h>
#include <cstdint>

#define N_NODES 50000
#define CH 64

__device__ float4 g_agg4[N_NODES * (CH / 4)];
__device__ int g_ei_is64;

// ---------------------------------------------------------------------------
// Kernel 1: agg = x. Interleaved 4 float4/thread (grid-strided, MLP=4)
// + ballot dtype detect in block 0.
// ---------------------------------------------------------------------------
__global__ void init_agg_kernel(const float4* __restrict__ x4, int n4,
                                const int* __restrict__ ei32) {
    int S = gridDim.x * blockDim.x;
    int i = blockIdx.x * blockDim.x + threadIdx.x;
    int i1 = i + S, i2 = i + 2 * S, i3 = i + 3 * S;
    // n4 = 800000, S = 200192 -> i3 < n4 only partially; guard each
    if (i < n4) {
        float4 v0 = x4[i];
        float4 v1, v2, v3;
        bool b1 = i1 < n4, b2 = i2 < n4, b3 = i3 < n4;
        if (b1) v1 = x4[i1];
        if (b2) v2 = x4[i2];
        if (b3) v3 = x4[i3];
        g_agg4[i] = v0;
        if (b1) g_agg4[i1] = v1;
        if (b2) g_agg4[i2] = v2;
        if (b3) g_agg4[i3] = v3;
    }
    if (blockIdx.x == 0 && threadIdx.x < 32) {
        int lane = threadIdx.x;
        int bad = (ei32[2 * lane + 1] != 0) | (ei32[2 * (lane + 32) + 1] != 0);
        unsigned m = __ballot_sync(0xFFFFFFFFu, bad);
        if (lane == 0) g_ei_is64 = (m == 0u) ? 1 : 0;
    }
}

// ---------------------------------------------------------------------------
// Kernel 2: scatter-add. 4-lane group per edge; lane l handles float4
// indices 4k + l (k = 0..3): 4 independent gathers + 4 RED.v4 (MLP=4).
// Lanes 0-3 per instruction cover contiguous 64B.
// ---------------------------------------------------------------------------
__global__ void scatter_kernel(const float4* __restrict__ x4,
                               const void* __restrict__ ei_raw,
                               int nE) {
    int g = blockIdx.x * blockDim.x + threadIdx.x;
    int lane = g & 3;
    int edge = g >> 2;
    if (edge >= nE) return;

    long long src, dst;
    if (g_ei_is64) {
        const long long* ei = (const long long*)ei_raw;
        src = ei[edge];
        dst = ei[nE + edge];
    } else {
        const int* ei = (const int*)ei_raw;
        src = ei[edge];
        dst = ei[nE + edge];
    }
    if ((unsigned long long)src >= N_NODES || (unsigned long long)dst >= N_NODES)
        return;

    const float4* sp = x4 + src * 16 + lane;
    float4* dp = g_agg4 + dst * 16 + lane;
    float4 v0 = sp[0];
    float4 v1 = sp[4];
    float4 v2 = sp[8];
    float4 v3 = sp[12];
    asm volatile("red.global.add.v4.f32 [%0], {%1, %2, %3, %4};"
                 :: "l"(dp), "f"(v0.x), "f"(v0.y), "f"(v0.z), "f"(v0.w) : "memory");
    asm volatile("red.global.add.v4.f32 [%0], {%1, %2, %3, %4};"
                 :: "l"(dp + 4), "f"(v1.x), "f"(v1.y), "f"(v1.z), "f"(v1.w) : "memory");
    asm volatile("red.global.add.v4.f32 [%0], {%1, %2, %3, %4};"
                 :: "l"(dp + 8), "f"(v2.x), "f"(v2.y), "f"(v2.z), "f"(v2.w) : "memory");
    asm volatile("red.global.add.v4.f32 [%0], {%1, %2, %3, %4};"
                 :: "l"(dp + 12), "f"(v3.x), "f"(v3.y), "f"(v3.z), "f"(v3.w) : "memory");
}

// ---------------------------------------------------------------------------
// Kernel 3: out = relu(h @ W^T + b).  (unchanged from R11 — proven)
// ---------------------------------------------------------------------------
#define GROWS 128
#define GTHREADS 128
#define H_STRIDE4 17
#define WT_STRIDE 72
#define SMEM_BYTES ((GROWS * H_STRIDE4 * 4 + 64 * WT_STRIDE) * 4)

__device__ __forceinline__ unsigned long long splat_f32x2(float v) {
    unsigned long long d;
    unsigned u = __float_as_uint(v);
    asm("mov.b64 %0, {%1, %1};" : "=l"(d) : "r"(u));
    return d;
}
__device__ __forceinline__ unsigned long long pack_f32x2(float lo, float hi) {
    unsigned long long d;
    asm("mov.b64 %0, {%1, %2};" : "=l"(d) : "r"(__float_as_uint(lo)), "r"(__float_as_uint(hi)));
    return d;
}
#define FFMA2(acc, a, b) \
    asm("fma.rn.f32x2 %0, %1, %2, %0;" : "+l"(acc) : "l"(a), "l"(b))

__global__ void __launch_bounds__(GTHREADS) gemm_relu_kernel(
    const float* __restrict__ W,
    const float* __restrict__ b,
    float* __restrict__ out)
{
    extern __shared__ float smem[];
    float4* sH4 = reinterpret_cast<float4*>(smem);
    float*  sWT = smem + GROWS * H_STRIDE4 * 4;

    int t = threadIdx.x;
    int r0 = blockIdx.x * GROWS;

    #pragma unroll
    for (int k = 0; k < 32; k++) {
        int idx = t + k * 128;
        int o = idx >> 6;
        int i = idx & 63;
        sWT[i * WT_STRIDE + o] = W[idx];
    }
    #pragma unroll
    for (int k = 0; k < 16; k++) {
        int idx = t + k * 128;
        int row = idx >> 4;
        int c4  = idx & 15;
        int grow = r0 + row;
        float4 v = (grow < N_NODES) ? g_agg4[grow * 16 + c4]
                                    : make_float4(0.f, 0.f, 0.f, 0.f);
        int c4s = c4 ^ ((row >> 3) & 15);
        sH4[row * H_STRIDE4 + c4s] = v;
    }
    __syncthreads();

    int tr = t >> 3;
    int tc = t & 7;
    int rbase = tr * 8;
    int obase = tc * 8;

    unsigned long long acc[8][4];
    {
        unsigned long long bp[4];
        #pragma unroll
        for (int cp = 0; cp < 4; cp++)
            bp[cp] = pack_f32x2(b[obase + 2 * cp], b[obase + 2 * cp + 1]);
        #pragma unroll
        for (int r = 0; r < 8; r++)
            #pragma unroll
            for (int cp = 0; cp < 4; cp++)
                acc[r][cp] = bp[cp];
    }

    #pragma unroll 4
    for (int q = 0; q < 16; q++) {
        float4 hr[8];
        int qs = q ^ tr;
        #pragma unroll
        for (int r = 0; r < 8; r++)
            hr[r] = sH4[(rbase + r) * H_STRIDE4 + qs];
        #pragma unroll
        for (int kk = 0; kk < 4; kk++) {
            int i = 4 * q + kk;
            ulonglong2 wA = *reinterpret_cast<const ulonglong2*>(&sWT[i * WT_STRIDE + obase]);
            ulonglong2 wB = *reinterpret_cast<const ulonglong2*>(&sWT[i * WT_STRIDE + obase + 4]);
            unsigned long long wp[4] = {wA.x, wA.y, wB.x, wB.y};
            #pragma unroll
            for (int r = 0; r < 8; r++) {
                float hv = (kk == 0) ? hr[r].x : (kk == 1) ? hr[r].y
                         : (kk == 2) ? hr[r].z : hr[r].w;
                unsigned long long h2 = splat_f32x2(hv);
                #pragma unroll
                for (int cp = 0; cp < 4; cp++)
                    FFMA2(acc[r][cp], h2, wp[cp]);
            }
        }
    }

    #pragma unroll
    for (int r = 0; r < 8; r++) {
        int row = r0 + rbase + r;
        if (row < N_NODES) {
            float v[8];
            #pragma unroll
            for (int cp = 0; cp < 4; cp++) {
                float2 f = *reinterpret_cast<float2*>(&acc[r][cp]);
                v[2 * cp]     = fmaxf(f.x, 0.f);
                v[2 * cp + 1] = fmaxf(f.y, 0.f);
            }
            float4* o4 = reinterpret_cast<float4*>(out + row * CH + obase);
            o4[0] = make_float4(v[0], v[1], v[2], v[3]);
            o4[1] = make_float4(v[4], v[5], v[6], v[7]);
        }
    }
}

// ---------------------------------------------------------------------------
extern "C" void kernel_launch(void* const* d_in, const int* in_sizes, int n_in,
                              void* d_out, int out_size) {
    const float* x  = (const float*)d_in[0];
    const void*  ei = d_in[1];
    const float* W  = (const float*)d_in[2];
    const float* b  = (const float*)d_in[3];
    float* out = (float*)d_out;

    int nE = in_sizes[1] / 2;                 // 800000
    int n4 = (N_NODES * CH) / 4;              // 800000 float4

    static bool attr_done = false;
    if (!attr_done) {
        cudaFuncSetAttribute(gemm_relu_kernel,
                             cudaFuncAttributeMaxDynamicSharedMemorySize,
                             SMEM_BYTES);
        attr_done = true;
    }

    int ithreads = (n4 + 3) / 4;
    init_agg_kernel<<<(ithreads + 255) / 256, 256>>>(
        reinterpret_cast<const float4*>(x), n4, (const int*)ei);

    long long threads = (long long)nE * 4;
    int blocks = (int)((threads + 255) / 256);
    scatter_kernel<<<blocks, 256>>>(
        reinterpret_cast<const float4*>(x), ei, nE);

    int gblocks = (N_NODES + GROWS - 1) / GROWS;
    gemm_relu_kernel<<<gblocks, GTHREADS, SMEM_BYTES>>>(W, b, out);
}

// round 13
// speedup vs baseline: 1.0665x; 1.0665x over previous
#include <cuda_runtime.h>
#include <cstdint>

#define N_NODES 50000
#define CH 64

// sum-only accumulator (zeroed by memset node; x added during GEMM staging)
__device__ float4 g_agg4[N_NODES * (CH / 4)];
__device__ int g_ei_is64;

// ---------------------------------------------------------------------------
// Kernel 0: ballot dtype detect (tiny; ~launch overhead only)
// ---------------------------------------------------------------------------
__global__ void detect_kernel(const int* __restrict__ ei32) {
    int lane = threadIdx.x;
    int bad = (ei32[2 * lane + 1] != 0) | (ei32[2 * (lane + 32) + 1] != 0);
    unsigned m = __ballot_sync(0xFFFFFFFFu, bad);
    if (lane == 0) g_ei_is64 = (m == 0u) ? 1 : 0;
}

// ---------------------------------------------------------------------------
// Kernel 1: scatter-add. 8-lane group per edge; lane owns float4 j and j+8.
// (R11 config — proven best: MLP=2, at the LTS traffic floor)
// ---------------------------------------------------------------------------
__global__ void scatter_kernel(const float4* __restrict__ x4,
                               const void* __restrict__ ei_raw,
                               int nE) {
    int g = blockIdx.x * blockDim.x + threadIdx.x;
    int lane = g & 7;
    int edge = g >> 3;
    if (edge >= nE) return;

    long long src, dst;
    if (g_ei_is64) {
        const long long* ei = (const long long*)ei_raw;
        src = ei[edge];
        dst = ei[nE + edge];
    } else {
        const int* ei = (const int*)ei_raw;
        src = ei[edge];
        dst = ei[nE + edge];
    }
    if ((unsigned long long)src >= N_NODES || (unsigned long long)dst >= N_NODES)
        return;

    float4 v0 = x4[src * 16 + lane];
    float4 v1 = x4[src * 16 + lane + 8];
    float4* d0 = g_agg4 + dst * 16 + lane;
    float4* d1 = g_agg4 + dst * 16 + lane + 8;
    asm volatile("red.global.add.v4.f32 [%0], {%1, %2, %3, %4};"
                 :: "l"(d0), "f"(v0.x), "f"(v0.y), "f"(v0.z), "f"(v0.w)
                 : "memory");
    asm volatile("red.global.add.v4.f32 [%0], {%1, %2, %3, %4};"
                 :: "l"(d1), "f"(v1.x), "f"(v1.y), "f"(v1.z), "f"(v1.w)
                 : "memory");
}

// ---------------------------------------------------------------------------
// Kernel 2: out = relu((x + agg) @ W^T + b).
// Coalesced staging of h = x + agg (both streams L2-resident), XOR-swizzled
// sH; FFMA2 core (R11 — proven).
// ---------------------------------------------------------------------------
#define GROWS 128
#define GTHREADS 128
#define H_STRIDE4 17
#define WT_STRIDE 72
#define SMEM_BYTES ((GROWS * H_STRIDE4 * 4 + 64 * WT_STRIDE) * 4)

__device__ __forceinline__ unsigned long long splat_f32x2(float v) {
    unsigned long long d;
    unsigned u = __float_as_uint(v);
    asm("mov.b64 %0, {%1, %1};" : "=l"(d) : "r"(u));
    return d;
}
__device__ __forceinline__ unsigned long long pack_f32x2(float lo, float hi) {
    unsigned long long d;
    asm("mov.b64 %0, {%1, %2};" : "=l"(d) : "r"(__float_as_uint(lo)), "r"(__float_as_uint(hi)));
    return d;
}
#define FFMA2(acc, a, b) \
    asm("fma.rn.f32x2 %0, %1, %2, %0;" : "+l"(acc) : "l"(a), "l"(b))

__global__ void __launch_bounds__(GTHREADS) gemm_relu_kernel(
    const float4* __restrict__ x4,
    const float* __restrict__ W,
    const float* __restrict__ b,
    float* __restrict__ out)
{
    extern __shared__ float smem[];
    float4* sH4 = reinterpret_cast<float4*>(smem);
    float*  sWT = smem + GROWS * H_STRIDE4 * 4;

    int t = threadIdx.x;
    int r0 = blockIdx.x * GROWS;

    #pragma unroll
    for (int k = 0; k < 32; k++) {
        int idx = t + k * 128;
        int o = idx >> 6;
        int i = idx & 63;
        sWT[i * WT_STRIDE + o] = W[idx];
    }
    #pragma unroll
    for (int k = 0; k < 16; k++) {
        int idx = t + k * 128;
        int row = idx >> 4;
        int c4  = idx & 15;
        int grow = r0 + row;
        float4 v = make_float4(0.f, 0.f, 0.f, 0.f);
        if (grow < N_NODES) {
            float4 vx = x4[grow * 16 + c4];
            float4 va = g_agg4[grow * 16 + c4];
            v = make_float4(vx.x + va.x, vx.y + va.y, vx.z + va.z, vx.w + va.w);
        }
        int c4s = c4 ^ ((row >> 3) & 15);
        sH4[row * H_STRIDE4 + c4s] = v;
    }
    __syncthreads();

    int tr = t >> 3;
    int tc = t & 7;
    int rbase = tr * 8;
    int obase = tc * 8;

    unsigned long long acc[8][4];
    {
        unsigned long long bp[4];
        #pragma unroll
        for (int cp = 0; cp < 4; cp++)
            bp[cp] = pack_f32x2(b[obase + 2 * cp], b[obase + 2 * cp + 1]);
        #pragma unroll
        for (int r = 0; r < 8; r++)
            #pragma unroll
            for (int cp = 0; cp < 4; cp++)
                acc[r][cp] = bp[cp];
    }

    #pragma unroll 4
    for (int q = 0; q < 16; q++) {
        float4 hr[8];
        int qs = q ^ tr;
        #pragma unroll
        for (int r = 0; r < 8; r++)
            hr[r] = sH4[(rbase + r) * H_STRIDE4 + qs];
        #pragma unroll
        for (int kk = 0; kk < 4; kk++) {
            int i = 4 * q + kk;
            ulonglong2 wA = *reinterpret_cast<const ulonglong2*>(&sWT[i * WT_STRIDE + obase]);
            ulonglong2 wB = *reinterpret_cast<const ulonglong2*>(&sWT[i * WT_STRIDE + obase + 4]);
            unsigned long long wp[4] = {wA.x, wA.y, wB.x, wB.y};
            #pragma unroll
            for (int r = 0; r < 8; r++) {
                float hv = (kk == 0) ? hr[r].x : (kk == 1) ? hr[r].y
                         : (kk == 2) ? hr[r].z : hr[r].w;
                unsigned long long h2 = splat_f32x2(hv);
                #pragma unroll
                for (int cp = 0; cp < 4; cp++)
                    FFMA2(acc[r][cp], h2, wp[cp]);
            }
        }
    }

    #pragma unroll
    for (int r = 0; r < 8; r++) {
        int row = r0 + rbase + r;
        if (row < N_NODES) {
            float v[8];
            #pragma unroll
            for (int cp = 0; cp < 4; cp++) {
                float2 f = *reinterpret_cast<float2*>(&acc[r][cp]);
                v[2 * cp]     = fmaxf(f.x, 0.f);
                v[2 * cp + 1] = fmaxf(f.y, 0.f);
            }
            float4* o4 = reinterpret_cast<float4*>(out + row * CH + obase);
            o4[0] = make_float4(v[0], v[1], v[2], v[3]);
            o4[1] = make_float4(v[4], v[5], v[6], v[7]);
        }
    }
}

// ---------------------------------------------------------------------------
extern "C" void kernel_launch(void* const* d_in, const int* in_sizes, int n_in,
                              void* d_out, int out_size) {
    const float* x  = (const float*)d_in[0];
    const void*  ei = d_in[1];
    const float* W  = (const float*)d_in[2];
    const float* b  = (const float*)d_in[3];
    float* out = (float*)d_out;

    int nE = in_sizes[1] / 2;                 // 800000

    static bool attr_done = false;
    static void* agg_ptr = nullptr;
    if (!attr_done) {
        cudaFuncSetAttribute(gemm_relu_kernel,
                             cudaFuncAttributeMaxDynamicSharedMemorySize,
                             SMEM_BYTES);
        cudaGetSymbolAddress(&agg_ptr, g_agg4);
        attr_done = true;
    }

    detect_kernel<<<1, 32>>>((const int*)ei);
    cudaMemsetAsync(agg_ptr, 0, sizeof(float4) * N_NODES * (CH / 4));

    long long threads = (long long)nE * 8;
    int blocks = (int)((threads + 255) / 256);
    scatter_kernel<<<blocks, 256>>>(
        reinterpret_cast<const float4*>(x), ei, nE);

    int gblocks = (N_NODES + GROWS - 1) / GROWS;
    gemm_relu_kernel<<<gblocks, GTHREADS, SMEM_BYTES>>>(
        reinterpret_cast<const float4*>(x), W, b, out);
}

// round 14
// speedup vs baseline: 1.0918x; 1.0237x over previous
#include <cuda_runtime.h>
#include <cstdint>

#define N_NODES 50000
#define CH 64

// sum-only accumulator (zeroed by memset node; x added during GEMM staging)
__device__ float4 g_agg4[N_NODES * (CH / 4)];

// ---------------------------------------------------------------------------
// Kernel 1: scatter-add. 8-lane group per edge; lane owns float4 j and j+8.
// (MLP=2 — proven optimum; at the LTS traffic floor)
// Edge-index dtype detected INLINE per warp: int64 indices < 2^31 have every
// odd 32-bit word zero; 32 random int32 node ids all being zero ~ impossible.
// Cost: 1 hot LDG + ballot per warp (cache lines L1-resident after first use).
// ---------------------------------------------------------------------------
__global__ void scatter_kernel(const float4* __restrict__ x4,
                               const void* __restrict__ ei_raw,
                               int nE) {
    const int* ei32 = (const int*)ei_raw;
    int wlane = threadIdx.x & 31;
    int bad = (ei32[2 * wlane + 1] != 0);
    unsigned m = __ballot_sync(0xFFFFFFFFu, bad);
    bool is64 = (m == 0u);

    int g = blockIdx.x * blockDim.x + threadIdx.x;
    int lane = g & 7;
    int edge = g >> 3;
    if (edge >= nE) return;

    long long src, dst;
    if (is64) {
        const long long* ei = (const long long*)ei_raw;
        src = ei[edge];
        dst = ei[nE + edge];
    } else {
        src = ei32[edge];
        dst = ei32[nE + edge];
    }
    if ((unsigned long long)src >= N_NODES || (unsigned long long)dst >= N_NODES)
        return;

    float4 v0 = x4[src * 16 + lane];
    float4 v1 = x4[src * 16 + lane + 8];
    float4* d0 = g_agg4 + dst * 16 + lane;
    float4* d1 = g_agg4 + dst * 16 + lane + 8;
    asm volatile("red.global.add.v4.f32 [%0], {%1, %2, %3, %4};"
                 :: "l"(d0), "f"(v0.x), "f"(v0.y), "f"(v0.z), "f"(v0.w)
                 : "memory");
    asm volatile("red.global.add.v4.f32 [%0], {%1, %2, %3, %4};"
                 :: "l"(d1), "f"(v1.x), "f"(v1.y), "f"(v1.z), "f"(v1.w)
                 : "memory");
}

// ---------------------------------------------------------------------------
// Kernel 2: out = relu((x + agg) @ W^T + b).
// Coalesced staging of h = x + agg (both streams L2-resident), XOR-swizzled
// sH; FFMA2 core.
// ---------------------------------------------------------------------------
#define GROWS 128
#define GTHREADS 128
#define H_STRIDE4 17
#define WT_STRIDE 72
#define SMEM_BYTES ((GROWS * H_STRIDE4 * 4 + 64 * WT_STRIDE) * 4)

__device__ __forceinline__ unsigned long long splat_f32x2(float v) {
    unsigned long long d;
    unsigned u = __float_as_uint(v);
    asm("mov.b64 %0, {%1, %1};" : "=l"(d) : "r"(u));
    return d;
}
__device__ __forceinline__ unsigned long long pack_f32x2(float lo, float hi) {
    unsigned long long d;
    asm("mov.b64 %0, {%1, %2};" : "=l"(d) : "r"(__float_as_uint(lo)), "r"(__float_as_uint(hi)));
    return d;
}
#define FFMA2(acc, a, b) \
    asm("fma.rn.f32x2 %0, %1, %2, %0;" : "+l"(acc) : "l"(a), "l"(b))

__global__ void __launch_bounds__(GTHREADS) gemm_relu_kernel(
    const float4* __restrict__ x4,
    const float* __restrict__ W,
    const float* __restrict__ b,
    float* __restrict__ out)
{
    extern __shared__ float smem[];
    float4* sH4 = reinterpret_cast<float4*>(smem);
    float*  sWT = smem + GROWS * H_STRIDE4 * 4;

    int t = threadIdx.x;
    int r0 = blockIdx.x * GROWS;

    #pragma unroll
    for (int k = 0; k < 32; k++) {
        int idx = t + k * 128;
        int o = idx >> 6;
        int i = idx & 63;
        sWT[i * WT_STRIDE + o] = W[idx];
    }
    #pragma unroll
    for (int k = 0; k < 16; k++) {
        int idx = t + k * 128;
        int row = idx >> 4;
        int c4  = idx & 15;
        int grow = r0 + row;
        float4 v = make_float4(0.f, 0.f, 0.f, 0.f);
        if (grow < N_NODES) {
            float4 vx = x4[grow * 16 + c4];
            float4 va = g_agg4[grow * 16 + c4];
            v = make_float4(vx.x + va.x, vx.y + va.y, vx.z + va.z, vx.w + va.w);
        }
        int c4s = c4 ^ ((row >> 3) & 15);
        sH4[row * H_STRIDE4 + c4s] = v;
    }
    __syncthreads();

    int tr = t >> 3;
    int tc = t & 7;
    int rbase = tr * 8;
    int obase = tc * 8;

    unsigned long long acc[8][4];
    {
        unsigned long long bp[4];
        #pragma unroll
        for (int cp = 0; cp < 4; cp++)
            bp[cp] = pack_f32x2(b[obase + 2 * cp], b[obase + 2 * cp + 1]);
        #pragma unroll
        for (int r = 0; r < 8; r++)
            #pragma unroll
            for (int cp = 0; cp < 4; cp++)
                acc[r][cp] = bp[cp];
    }

    #pragma unroll 4
    for (int q = 0; q < 16; q++) {
        float4 hr[8];
        int qs = q ^ tr;
        #pragma unroll
        for (int r = 0; r < 8; r++)
            hr[r] = sH4[(rbase + r) * H_STRIDE4 + qs];
        #pragma unroll
        for (int kk = 0; kk < 4; kk++) {
            int i = 4 * q + kk;
            ulonglong2 wA = *reinterpret_cast<const ulonglong2*>(&sWT[i * WT_STRIDE + obase]);
            ulonglong2 wB = *reinterpret_cast<const ulonglong2*>(&sWT[i * WT_STRIDE + obase + 4]);
            unsigned long long wp[4] = {wA.x, wA.y, wB.x, wB.y};
            #pragma unroll
            for (int r = 0; r < 8; r++) {
                float hv = (kk == 0) ? hr[r].x : (kk == 1) ? hr[r].y
                         : (kk == 2) ? hr[r].z : hr[r].w;
                unsigned long long h2 = splat_f32x2(hv);
                #pragma unroll
                for (int cp = 0; cp < 4; cp++)
                    FFMA2(acc[r][cp], h2, wp[cp]);
            }
        }
    }

    #pragma unroll
    for (int r = 0; r < 8; r++) {
        int row = r0 + rbase + r;
        if (row < N_NODES) {
            float v[8];
            #pragma unroll
            for (int cp = 0; cp < 4; cp++) {
                float2 f = *reinterpret_cast<float2*>(&acc[r][cp]);
                v[2 * cp]     = fmaxf(f.x, 0.f);
                v[2 * cp + 1] = fmaxf(f.y, 0.f);
            }
            float4* o4 = reinterpret_cast<float4*>(out + row * CH + obase);
            o4[0] = make_float4(v[0], v[1], v[2], v[3]);
            o4[1] = make_float4(v[4], v[5], v[6], v[7]);
        }
    }
}

// ---------------------------------------------------------------------------
extern "C" void kernel_launch(void* const* d_in, const int* in_sizes, int n_in,
                              void* d_out, int out_size) {
    const float* x  = (const float*)d_in[0];
    const void*  ei = d_in[1];
    const float* W  = (const float*)d_in[2];
    const float* b  = (const float*)d_in[3];
    float* out = (float*)d_out;

    int nE = in_sizes[1] / 2;                 // 800000

    static bool attr_done = false;
    static void* agg_ptr = nullptr;
    if (!attr_done) {
        cudaFuncSetAttribute(gemm_relu_kernel,
                             cudaFuncAttributeMaxDynamicSharedMemorySize,
                             SMEM_BYTES);
        cudaGetSymbolAddress(&agg_ptr, g_agg4);
        attr_done = true;
    }

    cudaMemsetAsync(agg_ptr, 0, sizeof(float4) * N_NODES * (CH / 4));

    long long threads = (long long)nE * 8;
    int blocks = (int)((threads + 255) / 256);
    scatter_kernel<<<blocks, 256>>>(
        reinterpret_cast<const float4*>(x), ei, nE);

    int gblocks = (N_NODES + GROWS - 1) / GROWS;
    gemm_relu_kernel<<<gblocks, GTHREADS, SMEM_BYTES>>>(
        reinterpret_cast<const float4*>(x), W, b, out);
}

// round 15
// speedup vs baseline: 1.1020x; 1.0094x over previous
#include <cuda_runtime.h>
#include <cstdint>

#define N_NODES 50000
#define CH 64

// sum-only accumulator (zeroed by memset node; x added during GEMM staging)
__device__ float4 g_agg4[N_NODES * (CH / 4)];

// ---------------------------------------------------------------------------
// Kernel 1: scatter-add. 8-lane group per edge; lane owns float4 j and j+8.
// (MLP=2 — proven optimum; at the LTS traffic floor)
// Edge-index dtype detected INLINE per warp (1 hot LDG + ballot).
// ---------------------------------------------------------------------------
__global__ void scatter_kernel(const float4* __restrict__ x4,
                               const void* __restrict__ ei_raw,
                               int nE) {
    const int* ei32 = (const int*)ei_raw;
    int wlane = threadIdx.x & 31;
    int bad = (ei32[2 * wlane + 1] != 0);
    unsigned m = __ballot_sync(0xFFFFFFFFu, bad);
    bool is64 = (m == 0u);

    int g = blockIdx.x * blockDim.x + threadIdx.x;
    int lane = g & 7;
    int edge = g >> 3;
    if (edge >= nE) return;

    long long src, dst;
    if (is64) {
        const long long* ei = (const long long*)ei_raw;
        src = ei[edge];
        dst = ei[nE + edge];
    } else {
        src = ei32[edge];
        dst = ei32[nE + edge];
    }
    if ((unsigned long long)src >= N_NODES || (unsigned long long)dst >= N_NODES)
        return;

    float4 v0 = x4[src * 16 + lane];
    float4 v1 = x4[src * 16 + lane + 8];
    float4* d0 = g_agg4 + dst * 16 + lane;
    float4* d1 = g_agg4 + dst * 16 + lane + 8;
    asm volatile("red.global.add.v4.f32 [%0], {%1, %2, %3, %4};"
                 :: "l"(d0), "f"(v0.x), "f"(v0.y), "f"(v0.z), "f"(v0.w)
                 : "memory");
    asm volatile("red.global.add.v4.f32 [%0], {%1, %2, %3, %4};"
                 :: "l"(d1), "f"(v1.x), "f"(v1.y), "f"(v1.z), "f"(v1.w)
                 : "memory");
}

// ---------------------------------------------------------------------------
// Kernel 2: out = relu((x + agg) @ W^T + b).
// 256 threads/block, 128 rows/block. Thread (tr=t>>4, tc=t&15) computes an
// 8x4 tile -> 2x warps/SM vs 8x8 config (occupancy was the binding limit:
// occ 15%, issue 32%). Per k: 1 LDS.128 of W = both FFMA2 operand pairs.
// ---------------------------------------------------------------------------
#define GROWS 128
#define GTHREADS 256
#define H_STRIDE4 17
#define WT_STRIDE 72
#define SMEM_BYTES ((GROWS * H_STRIDE4 * 4 + 64 * WT_STRIDE) * 4)

__device__ __forceinline__ unsigned long long splat_f32x2(float v) {
    unsigned long long d;
    unsigned u = __float_as_uint(v);
    asm("mov.b64 %0, {%1, %1};" : "=l"(d) : "r"(u));
    return d;
}
__device__ __forceinline__ unsigned long long pack_f32x2(float lo, float hi) {
    unsigned long long d;
    asm("mov.b64 %0, {%1, %2};" : "=l"(d) : "r"(__float_as_uint(lo)), "r"(__float_as_uint(hi)));
    return d;
}
#define FFMA2(acc, a, b) \
    asm("fma.rn.f32x2 %0, %1, %2, %0;" : "+l"(acc) : "l"(a), "l"(b))

__global__ void __launch_bounds__(GTHREADS) gemm_relu_kernel(
    const float4* __restrict__ x4,
    const float* __restrict__ W,
    const float* __restrict__ b,
    float* __restrict__ out)
{
    extern __shared__ float smem[];
    float4* sH4 = reinterpret_cast<float4*>(smem);
    float*  sWT = smem + GROWS * H_STRIDE4 * 4;

    int t = threadIdx.x;
    int r0 = blockIdx.x * GROWS;

    // Stage W transposed (k-major): 4096 / 256 = 16 each
    #pragma unroll
    for (int k = 0; k < 16; k++) {
        int idx = t + k * 256;
        int o = idx >> 6;
        int i = idx & 63;
        sWT[i * WT_STRIDE + o] = W[idx];
    }
    // Stage h = x + agg, coalesced, swizzled: 2048 f4 / 256 = 8 each
    #pragma unroll
    for (int k = 0; k < 8; k++) {
        int idx = t + k * 256;
        int row = idx >> 4;
        int c4  = idx & 15;
        int grow = r0 + row;
        float4 v = make_float4(0.f, 0.f, 0.f, 0.f);
        if (grow < N_NODES) {
            float4 vx = x4[grow * 16 + c4];
            float4 va = g_agg4[grow * 16 + c4];
            v = make_float4(vx.x + va.x, vx.y + va.y, vx.z + va.z, vx.w + va.w);
        }
        int c4s = c4 ^ ((row >> 3) & 15);
        sH4[row * H_STRIDE4 + c4s] = v;
    }
    __syncthreads();

    int tr = t >> 4;         // 0..15 -> row group (8 rows)
    int tc = t & 15;         // 0..15 -> col group (4 cols)
    int rbase = tr * 8;
    int obase = tc * 4;

    unsigned long long acc[8][2];
    {
        unsigned long long bp0 = pack_f32x2(b[obase],     b[obase + 1]);
        unsigned long long bp1 = pack_f32x2(b[obase + 2], b[obase + 3]);
        #pragma unroll
        for (int r = 0; r < 8; r++) { acc[r][0] = bp0; acc[r][1] = bp1; }
    }

    #pragma unroll 4
    for (int q = 0; q < 16; q++) {
        float4 hr[8];
        int qs = q ^ tr;                 // row>>3 == tr for our 8 rows
        #pragma unroll
        for (int r = 0; r < 8; r++)
            hr[r] = sH4[(rbase + r) * H_STRIDE4 + qs];
        #pragma unroll
        for (int kk = 0; kk < 4; kk++) {
            int i = 4 * q + kk;
            ulonglong2 wP = *reinterpret_cast<const ulonglong2*>(&sWT[i * WT_STRIDE + obase]);
            #pragma unroll
            for (int r = 0; r < 8; r++) {
                float hv = (kk == 0) ? hr[r].x : (kk == 1) ? hr[r].y
                         : (kk == 2) ? hr[r].z : hr[r].w;
                unsigned long long h2 = splat_f32x2(hv);
                FFMA2(acc[r][0], h2, wP.x);
                FFMA2(acc[r][1], h2, wP.y);
            }
        }
    }

    #pragma unroll
    for (int r = 0; r < 8; r++) {
        int row = r0 + rbase + r;
        if (row < N_NODES) {
            float2 f0 = *reinterpret_cast<float2*>(&acc[r][0]);
            float2 f1 = *reinterpret_cast<float2*>(&acc[r][1]);
            float4 v = make_float4(fmaxf(f0.x, 0.f), fmaxf(f0.y, 0.f),
                                   fmaxf(f1.x, 0.f), fmaxf(f1.y, 0.f));
            *reinterpret_cast<float4*>(out + row * CH + obase) = v;
        }
    }
}

// ---------------------------------------------------------------------------
extern "C" void kernel_launch(void* const* d_in, const int* in_sizes, int n_in,
                              void* d_out, int out_size) {
    const float* x  = (const float*)d_in[0];
    const void*  ei = d_in[1];
    const float* W  = (const float*)d_in[2];
    const float* b  = (const float*)d_in[3];
    float* out = (float*)d_out;

    int nE = in_sizes[1] / 2;                 // 800000

    static bool attr_done = false;
    static void* agg_ptr = nullptr;
    if (!attr_done) {
        cudaFuncSetAttribute(gemm_relu_kernel,
                             cudaFuncAttributeMaxDynamicSharedMemorySize,
                             SMEM_BYTES);
        cudaGetSymbolAddress(&agg_ptr, g_agg4);
        attr_done = true;
    }

    cudaMemsetAsync(agg_ptr, 0, sizeof(float4) * N_NODES * (CH / 4));

    long long threads = (long long)nE * 8;
    int blocks = (int)((threads + 255) / 256);
    scatter_kernel<<<blocks, 256>>>(
        reinterpret_cast<const float4*>(x), ei, nE);

    int gblocks = (N_NODES + GROWS - 1) / GROWS;
    gemm_relu_kernel<<<gblocks, GTHREADS, SMEM_BYTES>>>(
        reinterpret_cast<const float4*>(x), W, b, out);
}